// round 15
// baseline (speedup 1.0000x reference)
#include <cuda_runtime.h>

#define NN 100000
#define NE 1600000
#define DD 128
#define HH 32
#define NL 4

// ---- scratch (static device memory; no allocation) ----
__device__ __align__(16) float g_U[NN * HH];   // projected features (32-dim)
__device__ __align__(16) float g_Y1[NN * HH];
__device__ __align__(16) float g_Y2[NN * HH];
__device__ __align__(16) float g_Wc[3 * HH * HH];  // composed W1_{l+1}@W3_l, [k*32+c]
__device__ __align__(16) float g_bc[3 * HH];       // composed bias W1_{l+1}@b3_l
__device__ double g_s1[NL][2 * HH];                // per-layer BN1 stats (sum, sumsq)
__device__ double g_s2[NL][2 * HH];                // per-layer BN2 stats
__device__ int g_ei64;
// CSR scratch
__device__ int g_deg[NN];
__device__ int g_off[NN + 1];
__device__ int g_cursor[NN];
__device__ __align__(16) int g_csr[NE];
__device__ int g_bsum[128];

// ---------------------------------------------------------------------------
// prep: zero degree + stats; thread 0 detects edge dtype; blocks 0-2 compose
// Wc_t = W1_{t+1} @ W3_t (stored [k*32+c]) and bc_t = W1_{t+1} @ b3_t.
// ---------------------------------------------------------------------------
__global__ void k_prep(const long long* __restrict__ ei,
                       const float* __restrict__ W1, const float* __restrict__ W3,
                       const float* __restrict__ b3) {
    int gid = blockIdx.x * blockDim.x + threadIdx.x;
    if (gid == 0) {
        int is64 = 1;
        for (int i = 0; i < 16; i++) {
            long long v = ei[i];
            if (v < 0 || v >= (long long)NN) { is64 = 0; break; }
        }
        g_ei64 = is64;
    }
    if (gid < NN) g_deg[gid] = 0;
    if (gid < NL * 2 * HH) {
        ((double*)g_s1)[gid] = 0.0;
        ((double*)g_s2)[gid] = 0.0;
    }
    if (blockIdx.x < 3) {
        int t = blockIdx.x;
        for (int p = threadIdx.x; p < HH * HH; p += blockDim.x) {
            int c = p >> 5, k = p & 31;
            const float* w1 = W1 + (t + 1) * HH * DD + c * DD;
            const float* w3 = W3 + t * DD * HH;
            float acc = 0.f;
#pragma unroll 8
            for (int d = 0; d < DD; d++) acc = fmaf(w1[d], w3[d * HH + k], acc);
            g_Wc[t * HH * HH + k * HH + c] = acc;
        }
        if (threadIdx.x < HH) {
            const float* w1c = W1 + (t + 1) * HH * DD + threadIdx.x * DD;
            const float* b3t = b3 + t * DD;
            float a = 0.f;
            for (int d = 0; d < DD; d++) a = fmaf(w1c[d], b3t[d], a);
            g_bc[t * HH + threadIdx.x] = a;
        }
    }
}

__global__ void k_hist(const long long* __restrict__ ei) {
    int e = blockIdx.x * blockDim.x + threadIdx.x;
    if (e >= NE) return;
    int dst = g_ei64 ? (int)ei[NE + e] : ((const int*)ei)[NE + e];
    atomicAdd(&g_deg[dst], 1);
}

__global__ void k_scanA() {
    __shared__ int s[1024];
    int gid = blockIdx.x * 1024 + threadIdx.x;
    int v = (gid < NN) ? g_deg[gid] : 0;
    s[threadIdx.x] = v;
    __syncthreads();
    for (int d = 1; d < 1024; d <<= 1) {
        int t = (threadIdx.x >= d) ? s[threadIdx.x - d] : 0;
        __syncthreads();
        s[threadIdx.x] += t;
        __syncthreads();
    }
    if (gid < NN) g_cursor[gid] = s[threadIdx.x];
    if (threadIdx.x == 1023) g_bsum[blockIdx.x] = s[1023];
}

// scanC with inline scan of the 98 block sums (replaces separate scanB).
__global__ void k_scanC2() {
    __shared__ int sb[128];
    if (threadIdx.x < 128) sb[threadIdx.x] = (threadIdx.x < 98) ? g_bsum[threadIdx.x] : 0;
    __syncthreads();
    for (int d = 1; d < 128; d <<= 1) {
        int t = 0;
        if (threadIdx.x < 128 && threadIdx.x >= d) t = sb[threadIdx.x - d];
        __syncthreads();
        if (threadIdx.x < 128) sb[threadIdx.x] += t;
        __syncthreads();
    }
    int gid = blockIdx.x * blockDim.x + threadIdx.x;
    if (gid >= NN) return;
    int b = gid >> 10;
    int excl = g_cursor[gid] - g_deg[gid] + (b ? sb[b - 1] : 0);
    g_off[gid] = excl;
    g_cursor[gid] = excl;
    if (gid == 0) g_off[NN] = NE;
}

__global__ void k_fill(const long long* __restrict__ ei) {
    int e = blockIdx.x * blockDim.x + threadIdx.x;
    if (e >= NE) return;
    int src, dst;
    if (g_ei64) { src = (int)ei[e]; dst = (int)ei[NE + e]; }
    else { src = ((const int*)ei)[e]; dst = ((const int*)ei)[NE + e]; }
    int pos = atomicAdd(&g_cursor[dst], 1);
    g_csr[pos] = src;
}

// ---------------------------------------------------------------------------
// Inline BN-fold: derive (a, c) for 4 columns col=4*c4+j from stats.
// ---------------------------------------------------------------------------
__device__ __forceinline__ void bn_fold(const double* st, const float* gam,
                                        const float* bet, int c4,
                                        float4& a4, float4& c4v) {
    const double invN = 1.0 / (double)NN;
    float a[4], c[4];
#pragma unroll
    for (int j = 0; j < 4; j++) {
        int col = 4 * c4 + j;
        double m = st[col] * invN;
        double var = st[HH + col] * invN - m * m;
        float aa = gam[col] * rsqrtf((float)var + 1e-5f);
        a[j] = aa;
        c[j] = bet[col] - aa * (float)m;
    }
    a4 = make_float4(a[0], a[1], a[2], a[3]);
    c4v = make_float4(c[0], c[1], c[2], c[3]);
}

// ---------------------------------------------------------------------------
// GEMM1: U = X_in @ W1_0^T  (128 -> 32), no bias, no stats.
// ---------------------------------------------------------------------------
__global__ __launch_bounds__(256) void k_gemm1(const float4* __restrict__ Xin,
                                               const float* __restrict__ W1l) {
    __shared__ __align__(16) float Ws[DD * HH];  // Ws[k*32+c] = W1l[c*128+k]
    for (int i = threadIdx.x; i < DD * HH; i += 256) {
        int k = i >> 5, c = i & 31;
        Ws[k * 32 + c] = W1l[c * DD + k];
    }
    __syncthreads();
    const float4* Ws4 = (const float4*)Ws;
    int lane = threadIdx.x & 31;
    int rr = lane >> 3, c4 = lane & 7, base = lane & 24;
    int gw = blockIdx.x * 8 + (threadIdx.x >> 5);
    int nw = gridDim.x * 8;
    for (int rb = gw * 16; rb < NN; rb += nw * 16) {
        int row0 = rb + 4 * rr;
        float4 z[4][4];
#pragma unroll
        for (int i = 0; i < 4; i++)
#pragma unroll
            for (int m = 0; m < 4; m++)
                z[i][m] = Xin[(row0 + i) * 32 + c4 + 8 * m];
        float4 acc[4] = {{0,0,0,0},{0,0,0,0},{0,0,0,0},{0,0,0,0}};
#pragma unroll
        for (int m = 0; m < 4; m++) {
#pragma unroll 4
            for (int kc2 = 0; kc2 < 8; kc2++) {
                int srcl = base | kc2;
                int kk = (m * 8 + kc2) * 4;
                float4 w0 = Ws4[(kk + 0) * 8 + c4];
                float4 w1 = Ws4[(kk + 1) * 8 + c4];
                float4 w2 = Ws4[(kk + 2) * 8 + c4];
                float4 w3 = Ws4[(kk + 3) * 8 + c4];
#pragma unroll
                for (int i = 0; i < 4; i++) {
                    float a0 = __shfl_sync(0xffffffffu, z[i][m].x, srcl);
                    float a1 = __shfl_sync(0xffffffffu, z[i][m].y, srcl);
                    float a2 = __shfl_sync(0xffffffffu, z[i][m].z, srcl);
                    float a3 = __shfl_sync(0xffffffffu, z[i][m].w, srcl);
                    acc[i].x = fmaf(a0, w0.x, fmaf(a1, w1.x, fmaf(a2, w2.x, fmaf(a3, w3.x, acc[i].x))));
                    acc[i].y = fmaf(a0, w0.y, fmaf(a1, w1.y, fmaf(a2, w2.y, fmaf(a3, w3.y, acc[i].y))));
                    acc[i].z = fmaf(a0, w0.z, fmaf(a1, w1.z, fmaf(a2, w2.z, fmaf(a3, w3.z, acc[i].z))));
                    acc[i].w = fmaf(a0, w0.w, fmaf(a1, w1.w, fmaf(a2, w2.w, fmaf(a3, w3.w, acc[i].w))));
                }
            }
        }
#pragma unroll
        for (int i = 0; i < 4; i++)
            ((float4*)g_U)[(row0 + i) * 8 + c4] = acc[i];
    }
}

// ---------------------------------------------------------------------------
// 32-dim aggregation: Y1[n] = (1+eps_l)*U[n] + sum_{s in N(n)} U[s] + b1
// Warp per node; lane = column. Scalar __ldg index loads, unroll 8.
// ---------------------------------------------------------------------------
__global__ __launch_bounds__(256) void k_agg32(const float* __restrict__ eps, int l,
                                               const float* __restrict__ b1l) {
    __shared__ float ssum[8][HH], ssq[8][HH];
    int warp = threadIdx.x >> 5, lane = threadIdx.x & 31;
    int gw = blockIdx.x * 8 + warp;
    int nw = gridDim.x * 8;
    float s = 1.0f + eps[l];
    float bias = b1l[lane];
    float lsum = 0.f, lsq = 0.f;
    for (int n = gw; n < NN; n += nw) {
        int beg = g_off[n], end = g_off[n + 1];
        float acc = fmaf(s, g_U[n * HH + lane], bias);
        int e = beg;
        for (; e + 8 <= end; e += 8) {
            int s0 = __ldg(&g_csr[e + 0]), s1 = __ldg(&g_csr[e + 1]);
            int s2 = __ldg(&g_csr[e + 2]), s3 = __ldg(&g_csr[e + 3]);
            int s4 = __ldg(&g_csr[e + 4]), s5 = __ldg(&g_csr[e + 5]);
            int s6 = __ldg(&g_csr[e + 6]), s7 = __ldg(&g_csr[e + 7]);
            float v0 = g_U[s0 * HH + lane], v1 = g_U[s1 * HH + lane];
            float v2 = g_U[s2 * HH + lane], v3 = g_U[s3 * HH + lane];
            float v4 = g_U[s4 * HH + lane], v5 = g_U[s5 * HH + lane];
            float v6 = g_U[s6 * HH + lane], v7 = g_U[s7 * HH + lane];
            acc += ((v0 + v1) + (v2 + v3)) + ((v4 + v5) + (v6 + v7));
        }
        for (; e + 2 <= end; e += 2) {
            int s0 = __ldg(&g_csr[e + 0]), s1 = __ldg(&g_csr[e + 1]);
            acc += g_U[s0 * HH + lane] + g_U[s1 * HH + lane];
        }
        if (e < end) acc += g_U[__ldg(&g_csr[e]) * HH + lane];
        g_Y1[n * HH + lane] = acc;
        lsum += acc;
        lsq = fmaf(acc, acc, lsq);
    }
    ssum[warp][lane] = lsum;
    ssq[warp][lane] = lsq;
    __syncthreads();
    if (threadIdx.x < HH) {
        float a = 0.f, q = 0.f;
        for (int w = 0; w < 8; w++) { a += ssum[w][threadIdx.x]; q += ssq[w][threadIdx.x]; }
        atomicAdd(&g_s1[l][threadIdx.x], (double)a);
        atomicAdd(&g_s1[l][HH + threadIdx.x], (double)q);
    }
}

// ---------------------------------------------------------------------------
// Generic 32->32: out = relu(bn(in)) @ W^T + bias, BN fold inline.
// io: 0 -> g_Y1->g_Y2 (bn from g_s1[l], stats to g_s2[l]); 1 -> g_Y2->g_U (bn g_s2[l])
// trans >= 0: weight = g_Wc[trans], bias = g_bc[trans]; else W2l/b2l.
// ---------------------------------------------------------------------------
__global__ __launch_bounds__(256) void k_gemm32(int io, int l,
                                                const float* __restrict__ W2l,
                                                const float* __restrict__ b2l,
                                                const float* __restrict__ gam,
                                                const float* __restrict__ bet,
                                                int trans) {
    __shared__ __align__(16) float Ws[HH * HH];
    __shared__ float bsum[HH], bsq[HH];
    const float4* in = (io == 0) ? (const float4*)g_Y1 : (const float4*)g_Y2;
    float4* out = (io == 0) ? (float4*)g_Y2 : (float4*)g_U;
    const double* st = (io == 0) ? g_s1[l] : g_s2[l];
    int do_stats = (io == 0);
    if (trans >= 0) {
        for (int i = threadIdx.x; i < HH * HH; i += 256)
            Ws[i] = g_Wc[trans * HH * HH + i];
    } else {
        for (int i = threadIdx.x; i < HH * HH; i += 256) {
            int k = i >> 5, c = i & 31;
            Ws[k * 32 + c] = W2l[c * HH + k];
        }
    }
    if (threadIdx.x < HH) { bsum[threadIdx.x] = 0.f; bsq[threadIdx.x] = 0.f; }
    __syncthreads();
    const float4* Ws4 = (const float4*)Ws;
    int lane = threadIdx.x & 31;
    int rr = lane >> 3, c4 = lane & 7, base = lane & 24;
    int gw = blockIdx.x * 8 + (threadIdx.x >> 5);
    int nw = gridDim.x * 8;
    float4 bias = (trans >= 0) ? ((const float4*)(g_bc + trans * HH))[c4]
                               : ((const float4*)b2l)[c4];
    float4 ba, bc;
    bn_fold(st, gam, bet, c4, ba, bc);
    float4 ls = {0, 0, 0, 0}, lq = {0, 0, 0, 0};
    for (int rb = gw * 16; rb < NN; rb += nw * 16) {
        int row0 = rb + 4 * rr;
        float4 h[4];
#pragma unroll
        for (int i = 0; i < 4; i++) {
            float4 y = in[(row0 + i) * 8 + c4];
            h[i].x = fmaxf(fmaf(ba.x, y.x, bc.x), 0.f);
            h[i].y = fmaxf(fmaf(ba.y, y.y, bc.y), 0.f);
            h[i].z = fmaxf(fmaf(ba.z, y.z, bc.z), 0.f);
            h[i].w = fmaxf(fmaf(ba.w, y.w, bc.w), 0.f);
        }
        float4 acc[4] = {bias, bias, bias, bias};
#pragma unroll 4
        for (int kc2 = 0; kc2 < 8; kc2++) {
            int srcl = base | kc2;
            int kk = kc2 * 4;
            float4 w0 = Ws4[(kk + 0) * 8 + c4];
            float4 w1 = Ws4[(kk + 1) * 8 + c4];
            float4 w2 = Ws4[(kk + 2) * 8 + c4];
            float4 w3 = Ws4[(kk + 3) * 8 + c4];
#pragma unroll
            for (int i = 0; i < 4; i++) {
                float a0 = __shfl_sync(0xffffffffu, h[i].x, srcl);
                float a1 = __shfl_sync(0xffffffffu, h[i].y, srcl);
                float a2 = __shfl_sync(0xffffffffu, h[i].z, srcl);
                float a3 = __shfl_sync(0xffffffffu, h[i].w, srcl);
                acc[i].x = fmaf(a0, w0.x, fmaf(a1, w1.x, fmaf(a2, w2.x, fmaf(a3, w3.x, acc[i].x))));
                acc[i].y = fmaf(a0, w0.y, fmaf(a1, w1.y, fmaf(a2, w2.y, fmaf(a3, w3.y, acc[i].y))));
                acc[i].z = fmaf(a0, w0.z, fmaf(a1, w1.z, fmaf(a2, w2.z, fmaf(a3, w3.z, acc[i].z))));
                acc[i].w = fmaf(a0, w0.w, fmaf(a1, w1.w, fmaf(a2, w2.w, fmaf(a3, w3.w, acc[i].w))));
            }
        }
#pragma unroll
        for (int i = 0; i < 4; i++) {
            out[(row0 + i) * 8 + c4] = acc[i];
            if (do_stats) {
                ls.x += acc[i].x; ls.y += acc[i].y; ls.z += acc[i].z; ls.w += acc[i].w;
                lq.x = fmaf(acc[i].x, acc[i].x, lq.x); lq.y = fmaf(acc[i].y, acc[i].y, lq.y);
                lq.z = fmaf(acc[i].z, acc[i].z, lq.z); lq.w = fmaf(acc[i].w, acc[i].w, lq.w);
            }
        }
    }
    if (do_stats) {
        atomicAdd(&bsum[4 * c4 + 0], ls.x); atomicAdd(&bsum[4 * c4 + 1], ls.y);
        atomicAdd(&bsum[4 * c4 + 2], ls.z); atomicAdd(&bsum[4 * c4 + 3], ls.w);
        atomicAdd(&bsq[4 * c4 + 0], lq.x);  atomicAdd(&bsq[4 * c4 + 1], lq.y);
        atomicAdd(&bsq[4 * c4 + 2], lq.z);  atomicAdd(&bsq[4 * c4 + 3], lq.w);
        __syncthreads();
        if (threadIdx.x < HH) {
            atomicAdd(&g_s2[l][threadIdx.x], (double)bsum[threadIdx.x]);
            atomicAdd(&g_s2[l][HH + threadIdx.x], (double)bsq[threadIdx.x]);
        }
    }
}

// ---------------------------------------------------------------------------
// Final GEMM3: out = relu(bn2(Y2)) @ W3^T + b3  (32 -> 128), BN2 inline.
// ---------------------------------------------------------------------------
__global__ __launch_bounds__(256) void k_gemm3(int l,
                                               const float* __restrict__ W3l,
                                               const float* __restrict__ b3l,
                                               const float* __restrict__ gam,
                                               const float* __restrict__ bet,
                                               float4* __restrict__ Xout) {
    __shared__ __align__(16) float Wt[HH * DD];  // Wt[k*128+c] = W3l[c*32+k]
    for (int i = threadIdx.x; i < HH * DD; i += 256) {
        int c = i >> 5, k = i & 31;
        Wt[k * DD + c] = W3l[i];
    }
    __syncthreads();
    const float4* Wt4 = (const float4*)Wt;
    int lane = threadIdx.x & 31;
    int rr = lane >> 3, c4 = lane & 7, base = lane & 24;
    int gw = blockIdx.x * 8 + (threadIdx.x >> 5);
    int nw = gridDim.x * 8;
    float4 ba, bc;
    bn_fold(g_s2[l], gam, bet, c4, ba, bc);
    float4 bias[4];
#pragma unroll
    for (int u = 0; u < 4; u++) bias[u] = ((const float4*)b3l)[c4 + 8 * u];
    for (int rb = gw * 16; rb < NN; rb += nw * 16) {
        int row0 = rb + 4 * rr;
        float4 h[4];
#pragma unroll
        for (int i = 0; i < 4; i++) {
            float4 y = ((const float4*)g_Y2)[(row0 + i) * 8 + c4];
            h[i].x = fmaxf(fmaf(ba.x, y.x, bc.x), 0.f);
            h[i].y = fmaxf(fmaf(ba.y, y.y, bc.y), 0.f);
            h[i].z = fmaxf(fmaf(ba.z, y.z, bc.z), 0.f);
            h[i].w = fmaxf(fmaf(ba.w, y.w, bc.w), 0.f);
        }
        float4 acc[4][4];
#pragma unroll
        for (int i = 0; i < 4; i++)
#pragma unroll
            for (int u = 0; u < 4; u++) acc[i][u] = bias[u];
        for (int kc2 = 0; kc2 < 8; kc2++) {
            int srcl = base | kc2;
            int kk = kc2 * 4;
#pragma unroll
            for (int i = 0; i < 4; i++) {
                float a0 = __shfl_sync(0xffffffffu, h[i].x, srcl);
                float a1 = __shfl_sync(0xffffffffu, h[i].y, srcl);
                float a2 = __shfl_sync(0xffffffffu, h[i].z, srcl);
                float a3 = __shfl_sync(0xffffffffu, h[i].w, srcl);
#pragma unroll
                for (int u = 0; u < 4; u++) {
                    float4 w0 = Wt4[(kk + 0) * 32 + c4 + 8 * u];
                    float4 w1 = Wt4[(kk + 1) * 32 + c4 + 8 * u];
                    float4 w2 = Wt4[(kk + 2) * 32 + c4 + 8 * u];
                    float4 w3 = Wt4[(kk + 3) * 32 + c4 + 8 * u];
                    acc[i][u].x = fmaf(a0, w0.x, fmaf(a1, w1.x, fmaf(a2, w2.x, fmaf(a3, w3.x, acc[i][u].x))));
                    acc[i][u].y = fmaf(a0, w0.y, fmaf(a1, w1.y, fmaf(a2, w2.y, fmaf(a3, w3.y, acc[i][u].y))));
                    acc[i][u].z = fmaf(a0, w0.z, fmaf(a1, w1.z, fmaf(a2, w2.z, fmaf(a3, w3.z, acc[i][u].z))));
                    acc[i][u].w = fmaf(a0, w0.w, fmaf(a1, w1.w, fmaf(a2, w2.w, fmaf(a3, w3.w, acc[i][u].w))));
                }
            }
        }
#pragma unroll
        for (int i = 0; i < 4; i++) {
            float4* xo = Xout + (row0 + i) * 32 + c4;
            xo[0] = acc[i][0]; xo[8] = acc[i][1]; xo[16] = acc[i][2]; xo[24] = acc[i][3];
        }
    }
}

// ---------------------------------------------------------------------------
extern "C" void kernel_launch(void* const* d_in, const int* in_sizes, int n_in,
                              void* d_out, int out_size) {
    const float* X = (const float*)d_in[0];
    const long long* ei = (const long long*)d_in[1];
    const float* eps = (const float*)d_in[2];
    const float* W1 = (const float*)d_in[3];
    const float* b1 = (const float*)d_in[4];
    const float* g1 = (const float*)d_in[5];
    const float* bt1 = (const float*)d_in[6];
    const float* W2 = (const float*)d_in[7];
    const float* b2 = (const float*)d_in[8];
    const float* g2 = (const float*)d_in[9];
    const float* bt2 = (const float*)d_in[10];
    const float* W3 = (const float*)d_in[11];
    const float* b3 = (const float*)d_in[12];

    const int GB = 444;    // GEMM grid: 148 SMs x 3 blocks/SM (reg-limited residency), single wave
    const int AB = 1184;   // aggregation grid

    k_prep<<<392, 256>>>(ei, W1, W3, b3);
    k_hist<<<6250, 256>>>(ei);
    k_scanA<<<98, 1024>>>();
    k_scanC2<<<392, 256>>>();
    k_fill<<<6250, 256>>>(ei);

    k_gemm1<<<GB, 256>>>((const float4*)X, W1);   // U = X @ W1_0^T

    for (int l = 0; l < NL; l++) {
        k_agg32<<<AB, 256>>>(eps, l, b1 + l * HH);
        k_gemm32<<<GB, 256>>>(0, l, W2 + l * HH * HH, b2 + l * HH,
                              g1 + l * HH, bt1 + l * HH, -1);
        if (l < NL - 1) {
            k_gemm32<<<GB, 256>>>(1, l, (const float*)0, (const float*)0,
                                  g2 + l * HH, bt2 + l * HH, l);
        } else {
            k_gemm3<<<GB, 256>>>(l, W3 + l * DD * HH, b3 + l * DD,
                                 g2 + l * HH, bt2 + l * HH, (float4*)d_out);
        }
    }
}

// round 16
// speedup vs baseline: 1.1877x; 1.1877x over previous
#include <cuda_runtime.h>

#define NN 100000
#define NE 1600000
#define DD 128
#define HH 32
#define NL 4

// ---- scratch (static device memory; no allocation) ----
__device__ __align__(16) float g_U[NN * HH];   // projected features (32-dim)
__device__ __align__(16) float g_Y1[NN * HH];
__device__ __align__(16) float g_Y2[NN * HH];
__device__ __align__(16) float g_Wc[3 * HH * HH];  // composed W1_{l+1}@W3_l, [k*32+c]
__device__ __align__(16) float g_bc[3 * HH];       // composed bias W1_{l+1}@b3_l
__device__ double g_s1[NL][2 * HH];                // per-layer BN1 stats (sum, sumsq)
__device__ double g_s2[NL][2 * HH];                // per-layer BN2 stats
__device__ int g_ei64;
// CSR scratch
__device__ int g_deg[NN];
__device__ int g_off[NN + 1];
__device__ int g_cursor[NN];
__device__ __align__(16) int g_csr[NE];
__device__ int g_bsum[128];

// ---------------------------------------------------------------------------
// prep: zero degree + stats; thread 0 detects edge dtype; blocks 0-2 compose
// Wc_t = W1_{t+1} @ W3_t (stored [k*32+c]) and bc_t = W1_{t+1} @ b3_t.
// ---------------------------------------------------------------------------
__global__ void k_prep(const long long* __restrict__ ei,
                       const float* __restrict__ W1, const float* __restrict__ W3,
                       const float* __restrict__ b3) {
    int gid = blockIdx.x * blockDim.x + threadIdx.x;
    if (gid == 0) {
        int is64 = 1;
        for (int i = 0; i < 16; i++) {
            long long v = ei[i];
            if (v < 0 || v >= (long long)NN) { is64 = 0; break; }
        }
        g_ei64 = is64;
    }
    if (gid < NN) g_deg[gid] = 0;
    if (gid < NL * 2 * HH) {
        ((double*)g_s1)[gid] = 0.0;
        ((double*)g_s2)[gid] = 0.0;
    }
    if (blockIdx.x < 3) {
        int t = blockIdx.x;
        for (int p = threadIdx.x; p < HH * HH; p += blockDim.x) {
            int c = p >> 5, k = p & 31;
            const float* w1 = W1 + (t + 1) * HH * DD + c * DD;
            const float* w3 = W3 + t * DD * HH;
            float acc = 0.f;
#pragma unroll 8
            for (int d = 0; d < DD; d++) acc = fmaf(w1[d], w3[d * HH + k], acc);
            g_Wc[t * HH * HH + k * HH + c] = acc;
        }
        if (threadIdx.x < HH) {
            const float* w1c = W1 + (t + 1) * HH * DD + threadIdx.x * DD;
            const float* b3t = b3 + t * DD;
            float a = 0.f;
            for (int d = 0; d < DD; d++) a = fmaf(w1c[d], b3t[d], a);
            g_bc[t * HH + threadIdx.x] = a;
        }
    }
}

__global__ void k_hist(const long long* __restrict__ ei) {
    int e = blockIdx.x * blockDim.x + threadIdx.x;
    if (e >= NE) return;
    int dst = g_ei64 ? (int)ei[NE + e] : ((const int*)ei)[NE + e];
    atomicAdd(&g_deg[dst], 1);
}

__global__ void k_scanA() {
    __shared__ int s[1024];
    int gid = blockIdx.x * 1024 + threadIdx.x;
    int v = (gid < NN) ? g_deg[gid] : 0;
    s[threadIdx.x] = v;
    __syncthreads();
    for (int d = 1; d < 1024; d <<= 1) {
        int t = (threadIdx.x >= d) ? s[threadIdx.x - d] : 0;
        __syncthreads();
        s[threadIdx.x] += t;
        __syncthreads();
    }
    if (gid < NN) g_cursor[gid] = s[threadIdx.x];
    if (threadIdx.x == 1023) g_bsum[blockIdx.x] = s[1023];
}

// scanC with inline scan of the 98 block sums (replaces separate scanB).
__global__ void k_scanC2() {
    __shared__ int sb[128];
    if (threadIdx.x < 128) sb[threadIdx.x] = (threadIdx.x < 98) ? g_bsum[threadIdx.x] : 0;
    __syncthreads();
    for (int d = 1; d < 128; d <<= 1) {
        int t = 0;
        if (threadIdx.x < 128 && threadIdx.x >= d) t = sb[threadIdx.x - d];
        __syncthreads();
        if (threadIdx.x < 128) sb[threadIdx.x] += t;
        __syncthreads();
    }
    int gid = blockIdx.x * blockDim.x + threadIdx.x;
    if (gid >= NN) return;
    int b = gid >> 10;
    int excl = g_cursor[gid] - g_deg[gid] + (b ? sb[b - 1] : 0);
    g_off[gid] = excl;
    g_cursor[gid] = excl;
    if (gid == 0) g_off[NN] = NE;
}

__global__ void k_fill(const long long* __restrict__ ei) {
    int e = blockIdx.x * blockDim.x + threadIdx.x;
    if (e >= NE) return;
    int src, dst;
    if (g_ei64) { src = (int)ei[e]; dst = (int)ei[NE + e]; }
    else { src = ((const int*)ei)[e]; dst = ((const int*)ei)[NE + e]; }
    int pos = atomicAdd(&g_cursor[dst], 1);
    g_csr[pos] = src;
}

// ---------------------------------------------------------------------------
// Inline BN-fold: derive (a, c) for 4 columns col=4*c4+j from stats.
// ---------------------------------------------------------------------------
__device__ __forceinline__ void bn_fold(const double* st, const float* gam,
                                        const float* bet, int c4,
                                        float4& a4, float4& c4v) {
    const double invN = 1.0 / (double)NN;
    float a[4], c[4];
#pragma unroll
    for (int j = 0; j < 4; j++) {
        int col = 4 * c4 + j;
        double m = st[col] * invN;
        double var = st[HH + col] * invN - m * m;
        float aa = gam[col] * rsqrtf((float)var + 1e-5f);
        a[j] = aa;
        c[j] = bet[col] - aa * (float)m;
    }
    a4 = make_float4(a[0], a[1], a[2], a[3]);
    c4v = make_float4(c[0], c[1], c[2], c[3]);
}

// ---------------------------------------------------------------------------
// GEMM1: U = X_in @ W1_0^T  (128 -> 32), no bias, no stats.
// ---------------------------------------------------------------------------
__global__ __launch_bounds__(256) void k_gemm1(const float4* __restrict__ Xin,
                                               const float* __restrict__ W1l) {
    __shared__ __align__(16) float Ws[DD * HH];  // Ws[k*32+c] = W1l[c*128+k]
    for (int i = threadIdx.x; i < DD * HH; i += 256) {
        int k = i >> 5, c = i & 31;
        Ws[k * 32 + c] = W1l[c * DD + k];
    }
    __syncthreads();
    const float4* Ws4 = (const float4*)Ws;
    int lane = threadIdx.x & 31;
    int rr = lane >> 3, c4 = lane & 7, base = lane & 24;
    int gw = blockIdx.x * 8 + (threadIdx.x >> 5);
    int nw = gridDim.x * 8;
    for (int rb = gw * 16; rb < NN; rb += nw * 16) {
        int row0 = rb + 4 * rr;
        float4 z[4][4];
#pragma unroll
        for (int i = 0; i < 4; i++)
#pragma unroll
            for (int m = 0; m < 4; m++)
                z[i][m] = Xin[(row0 + i) * 32 + c4 + 8 * m];
        float4 acc[4] = {{0,0,0,0},{0,0,0,0},{0,0,0,0},{0,0,0,0}};
#pragma unroll
        for (int m = 0; m < 4; m++) {
#pragma unroll 4
            for (int kc2 = 0; kc2 < 8; kc2++) {
                int srcl = base | kc2;
                int kk = (m * 8 + kc2) * 4;
                float4 w0 = Ws4[(kk + 0) * 8 + c4];
                float4 w1 = Ws4[(kk + 1) * 8 + c4];
                float4 w2 = Ws4[(kk + 2) * 8 + c4];
                float4 w3 = Ws4[(kk + 3) * 8 + c4];
#pragma unroll
                for (int i = 0; i < 4; i++) {
                    float a0 = __shfl_sync(0xffffffffu, z[i][m].x, srcl);
                    float a1 = __shfl_sync(0xffffffffu, z[i][m].y, srcl);
                    float a2 = __shfl_sync(0xffffffffu, z[i][m].z, srcl);
                    float a3 = __shfl_sync(0xffffffffu, z[i][m].w, srcl);
                    acc[i].x = fmaf(a0, w0.x, fmaf(a1, w1.x, fmaf(a2, w2.x, fmaf(a3, w3.x, acc[i].x))));
                    acc[i].y = fmaf(a0, w0.y, fmaf(a1, w1.y, fmaf(a2, w2.y, fmaf(a3, w3.y, acc[i].y))));
                    acc[i].z = fmaf(a0, w0.z, fmaf(a1, w1.z, fmaf(a2, w2.z, fmaf(a3, w3.z, acc[i].z))));
                    acc[i].w = fmaf(a0, w0.w, fmaf(a1, w1.w, fmaf(a2, w2.w, fmaf(a3, w3.w, acc[i].w))));
                }
            }
        }
#pragma unroll
        for (int i = 0; i < 4; i++)
            ((float4*)g_U)[(row0 + i) * 8 + c4] = acc[i];
    }
}

// ---------------------------------------------------------------------------
// 32-dim aggregation: Y1[n] = (1+eps_l)*U[n] + sum_{s in N(n)} U[s] + b1
// Warp per node; lane = column. Scalar __ldg index loads, unroll 8.
// ---------------------------------------------------------------------------
__global__ __launch_bounds__(256) void k_agg32(const float* __restrict__ eps, int l,
                                               const float* __restrict__ b1l) {
    __shared__ float ssum[8][HH], ssq[8][HH];
    int warp = threadIdx.x >> 5, lane = threadIdx.x & 31;
    int gw = blockIdx.x * 8 + warp;
    int nw = gridDim.x * 8;
    float s = 1.0f + eps[l];
    float bias = b1l[lane];
    float lsum = 0.f, lsq = 0.f;
    for (int n = gw; n < NN; n += nw) {
        int beg = g_off[n], end = g_off[n + 1];
        float acc = fmaf(s, g_U[n * HH + lane], bias);
        int e = beg;
        for (; e + 8 <= end; e += 8) {
            int s0 = __ldg(&g_csr[e + 0]), s1 = __ldg(&g_csr[e + 1]);
            int s2 = __ldg(&g_csr[e + 2]), s3 = __ldg(&g_csr[e + 3]);
            int s4 = __ldg(&g_csr[e + 4]), s5 = __ldg(&g_csr[e + 5]);
            int s6 = __ldg(&g_csr[e + 6]), s7 = __ldg(&g_csr[e + 7]);
            float v0 = g_U[s0 * HH + lane], v1 = g_U[s1 * HH + lane];
            float v2 = g_U[s2 * HH + lane], v3 = g_U[s3 * HH + lane];
            float v4 = g_U[s4 * HH + lane], v5 = g_U[s5 * HH + lane];
            float v6 = g_U[s6 * HH + lane], v7 = g_U[s7 * HH + lane];
            acc += ((v0 + v1) + (v2 + v3)) + ((v4 + v5) + (v6 + v7));
        }
        for (; e + 2 <= end; e += 2) {
            int s0 = __ldg(&g_csr[e + 0]), s1 = __ldg(&g_csr[e + 1]);
            acc += g_U[s0 * HH + lane] + g_U[s1 * HH + lane];
        }
        if (e < end) acc += g_U[__ldg(&g_csr[e]) * HH + lane];
        g_Y1[n * HH + lane] = acc;
        lsum += acc;
        lsq = fmaf(acc, acc, lsq);
    }
    ssum[warp][lane] = lsum;
    ssq[warp][lane] = lsq;
    __syncthreads();
    if (threadIdx.x < HH) {
        float a = 0.f, q = 0.f;
        for (int w = 0; w < 8; w++) { a += ssum[w][threadIdx.x]; q += ssq[w][threadIdx.x]; }
        atomicAdd(&g_s1[l][threadIdx.x], (double)a);
        atomicAdd(&g_s1[l][HH + threadIdx.x], (double)q);
    }
}

// ---------------------------------------------------------------------------
// Generic 32->32: out = relu(bn(in)) @ W^T + bias, BN fold inline.
// io: 0 -> g_Y1->g_Y2 (bn from g_s1[l], stats to g_s2[l]); 1 -> g_Y2->g_U (bn g_s2[l])
// trans >= 0: weight = g_Wc[trans], bias = g_bc[trans]; else W2l/b2l.
// ---------------------------------------------------------------------------
__global__ __launch_bounds__(256) void k_gemm32(int io, int l,
                                                const float* __restrict__ W2l,
                                                const float* __restrict__ b2l,
                                                const float* __restrict__ gam,
                                                const float* __restrict__ bet,
                                                int trans) {
    __shared__ __align__(16) float Ws[HH * HH];
    __shared__ float bsum[HH], bsq[HH];
    const float4* in = (io == 0) ? (const float4*)g_Y1 : (const float4*)g_Y2;
    float4* out = (io == 0) ? (float4*)g_Y2 : (float4*)g_U;
    const double* st = (io == 0) ? g_s1[l] : g_s2[l];
    int do_stats = (io == 0);
    if (trans >= 0) {
        for (int i = threadIdx.x; i < HH * HH; i += 256)
            Ws[i] = g_Wc[trans * HH * HH + i];
    } else {
        for (int i = threadIdx.x; i < HH * HH; i += 256) {
            int k = i >> 5, c = i & 31;
            Ws[k * 32 + c] = W2l[c * HH + k];
        }
    }
    if (threadIdx.x < HH) { bsum[threadIdx.x] = 0.f; bsq[threadIdx.x] = 0.f; }
    __syncthreads();
    const float4* Ws4 = (const float4*)Ws;
    int lane = threadIdx.x & 31;
    int rr = lane >> 3, c4 = lane & 7, base = lane & 24;
    int gw = blockIdx.x * 8 + (threadIdx.x >> 5);
    int nw = gridDim.x * 8;
    float4 bias = (trans >= 0) ? ((const float4*)(g_bc + trans * HH))[c4]
                               : ((const float4*)b2l)[c4];
    float4 ba, bc;
    bn_fold(st, gam, bet, c4, ba, bc);
    float4 ls = {0, 0, 0, 0}, lq = {0, 0, 0, 0};
    for (int rb = gw * 16; rb < NN; rb += nw * 16) {
        int row0 = rb + 4 * rr;
        float4 h[4];
#pragma unroll
        for (int i = 0; i < 4; i++) {
            float4 y = in[(row0 + i) * 8 + c4];
            h[i].x = fmaxf(fmaf(ba.x, y.x, bc.x), 0.f);
            h[i].y = fmaxf(fmaf(ba.y, y.y, bc.y), 0.f);
            h[i].z = fmaxf(fmaf(ba.z, y.z, bc.z), 0.f);
            h[i].w = fmaxf(fmaf(ba.w, y.w, bc.w), 0.f);
        }
        float4 acc[4] = {bias, bias, bias, bias};
#pragma unroll 4
        for (int kc2 = 0; kc2 < 8; kc2++) {
            int srcl = base | kc2;
            int kk = kc2 * 4;
            float4 w0 = Ws4[(kk + 0) * 8 + c4];
            float4 w1 = Ws4[(kk + 1) * 8 + c4];
            float4 w2 = Ws4[(kk + 2) * 8 + c4];
            float4 w3 = Ws4[(kk + 3) * 8 + c4];
#pragma unroll
            for (int i = 0; i < 4; i++) {
                float a0 = __shfl_sync(0xffffffffu, h[i].x, srcl);
                float a1 = __shfl_sync(0xffffffffu, h[i].y, srcl);
                float a2 = __shfl_sync(0xffffffffu, h[i].z, srcl);
                float a3 = __shfl_sync(0xffffffffu, h[i].w, srcl);
                acc[i].x = fmaf(a0, w0.x, fmaf(a1, w1.x, fmaf(a2, w2.x, fmaf(a3, w3.x, acc[i].x))));
                acc[i].y = fmaf(a0, w0.y, fmaf(a1, w1.y, fmaf(a2, w2.y, fmaf(a3, w3.y, acc[i].y))));
                acc[i].z = fmaf(a0, w0.z, fmaf(a1, w1.z, fmaf(a2, w2.z, fmaf(a3, w3.z, acc[i].z))));
                acc[i].w = fmaf(a0, w0.w, fmaf(a1, w1.w, fmaf(a2, w2.w, fmaf(a3, w3.w, acc[i].w))));
            }
        }
#pragma unroll
        for (int i = 0; i < 4; i++) {
            out[(row0 + i) * 8 + c4] = acc[i];
            if (do_stats) {
                ls.x += acc[i].x; ls.y += acc[i].y; ls.z += acc[i].z; ls.w += acc[i].w;
                lq.x = fmaf(acc[i].x, acc[i].x, lq.x); lq.y = fmaf(acc[i].y, acc[i].y, lq.y);
                lq.z = fmaf(acc[i].z, acc[i].z, lq.z); lq.w = fmaf(acc[i].w, acc[i].w, lq.w);
            }
        }
    }
    if (do_stats) {
        atomicAdd(&bsum[4 * c4 + 0], ls.x); atomicAdd(&bsum[4 * c4 + 1], ls.y);
        atomicAdd(&bsum[4 * c4 + 2], ls.z); atomicAdd(&bsum[4 * c4 + 3], ls.w);
        atomicAdd(&bsq[4 * c4 + 0], lq.x);  atomicAdd(&bsq[4 * c4 + 1], lq.y);
        atomicAdd(&bsq[4 * c4 + 2], lq.z);  atomicAdd(&bsq[4 * c4 + 3], lq.w);
        __syncthreads();
        if (threadIdx.x < HH) {
            atomicAdd(&g_s2[l][threadIdx.x], (double)bsum[threadIdx.x]);
            atomicAdd(&g_s2[l][HH + threadIdx.x], (double)bsq[threadIdx.x]);
        }
    }
}

// ---------------------------------------------------------------------------
// Final GEMM3: out = relu(bn2(Y2)) @ W3^T + b3  (32 -> 128), BN2 inline.
// ---------------------------------------------------------------------------
__global__ __launch_bounds__(256) void k_gemm3(int l,
                                               const float* __restrict__ W3l,
                                               const float* __restrict__ b3l,
                                               const float* __restrict__ gam,
                                               const float* __restrict__ bet,
                                               float4* __restrict__ Xout) {
    __shared__ __align__(16) float Wt[HH * DD];  // Wt[k*128+c] = W3l[c*32+k]
    for (int i = threadIdx.x; i < HH * DD; i += 256) {
        int c = i >> 5, k = i & 31;
        Wt[k * DD + c] = W3l[i];
    }
    __syncthreads();
    const float4* Wt4 = (const float4*)Wt;
    int lane = threadIdx.x & 31;
    int rr = lane >> 3, c4 = lane & 7, base = lane & 24;
    int gw = blockIdx.x * 8 + (threadIdx.x >> 5);
    int nw = gridDim.x * 8;
    float4 ba, bc;
    bn_fold(g_s2[l], gam, bet, c4, ba, bc);
    float4 bias[4];
#pragma unroll
    for (int u = 0; u < 4; u++) bias[u] = ((const float4*)b3l)[c4 + 8 * u];
    for (int rb = gw * 16; rb < NN; rb += nw * 16) {
        int row0 = rb + 4 * rr;
        float4 h[4];
#pragma unroll
        for (int i = 0; i < 4; i++) {
            float4 y = ((const float4*)g_Y2)[(row0 + i) * 8 + c4];
            h[i].x = fmaxf(fmaf(ba.x, y.x, bc.x), 0.f);
            h[i].y = fmaxf(fmaf(ba.y, y.y, bc.y), 0.f);
            h[i].z = fmaxf(fmaf(ba.z, y.z, bc.z), 0.f);
            h[i].w = fmaxf(fmaf(ba.w, y.w, bc.w), 0.f);
        }
        float4 acc[4][4];
#pragma unroll
        for (int i = 0; i < 4; i++)
#pragma unroll
            for (int u = 0; u < 4; u++) acc[i][u] = bias[u];
        for (int kc2 = 0; kc2 < 8; kc2++) {
            int srcl = base | kc2;
            int kk = kc2 * 4;
#pragma unroll
            for (int i = 0; i < 4; i++) {
                float a0 = __shfl_sync(0xffffffffu, h[i].x, srcl);
                float a1 = __shfl_sync(0xffffffffu, h[i].y, srcl);
                float a2 = __shfl_sync(0xffffffffu, h[i].z, srcl);
                float a3 = __shfl_sync(0xffffffffu, h[i].w, srcl);
#pragma unroll
                for (int u = 0; u < 4; u++) {
                    float4 w0 = Wt4[(kk + 0) * 32 + c4 + 8 * u];
                    float4 w1 = Wt4[(kk + 1) * 32 + c4 + 8 * u];
                    float4 w2 = Wt4[(kk + 2) * 32 + c4 + 8 * u];
                    float4 w3 = Wt4[(kk + 3) * 32 + c4 + 8 * u];
                    acc[i][u].x = fmaf(a0, w0.x, fmaf(a1, w1.x, fmaf(a2, w2.x, fmaf(a3, w3.x, acc[i][u].x))));
                    acc[i][u].y = fmaf(a0, w0.y, fmaf(a1, w1.y, fmaf(a2, w2.y, fmaf(a3, w3.y, acc[i][u].y))));
                    acc[i][u].z = fmaf(a0, w0.z, fmaf(a1, w1.z, fmaf(a2, w2.z, fmaf(a3, w3.z, acc[i][u].z))));
                    acc[i][u].w = fmaf(a0, w0.w, fmaf(a1, w1.w, fmaf(a2, w2.w, fmaf(a3, w3.w, acc[i][u].w))));
                }
            }
        }
#pragma unroll
        for (int i = 0; i < 4; i++) {
            float4* xo = Xout + (row0 + i) * 32 + c4;
            xo[0] = acc[i][0]; xo[8] = acc[i][1]; xo[16] = acc[i][2]; xo[24] = acc[i][3];
        }
    }
}

// ---------------------------------------------------------------------------
extern "C" void kernel_launch(void* const* d_in, const int* in_sizes, int n_in,
                              void* d_out, int out_size) {
    const float* X = (const float*)d_in[0];
    const long long* ei = (const long long*)d_in[1];
    const float* eps = (const float*)d_in[2];
    const float* W1 = (const float*)d_in[3];
    const float* b1 = (const float*)d_in[4];
    const float* g1 = (const float*)d_in[5];
    const float* bt1 = (const float*)d_in[6];
    const float* W2 = (const float*)d_in[7];
    const float* b2 = (const float*)d_in[8];
    const float* g2 = (const float*)d_in[9];
    const float* bt2 = (const float*)d_in[10];
    const float* W3 = (const float*)d_in[11];
    const float* b3 = (const float*)d_in[12];

    const int GB = 296;    // GEMM grid: 148 SMs x 2 resident blocks/SM, single wave
    const int AB = 1184;   // aggregation grid

    // Fork: gemm1 (depends only on X, W1) runs concurrently with the CSR build.
    cudaStream_t s2;
    cudaEvent_t eFork, eJoin;
    cudaStreamCreateWithFlags(&s2, cudaStreamNonBlocking);
    cudaEventCreateWithFlags(&eFork, cudaEventDisableTiming);
    cudaEventCreateWithFlags(&eJoin, cudaEventDisableTiming);

    cudaEventRecord(eFork, 0);            // fork point on capture (null) stream
    cudaStreamWaitEvent(s2, eFork, 0);
    k_gemm1<<<GB, 256, 0, s2>>>((const float4*)X, W1);   // U = X @ W1_0^T
    cudaEventRecord(eJoin, s2);

    k_prep<<<392, 256>>>(ei, W1, W3, b3);
    k_hist<<<6250, 256>>>(ei);
    k_scanA<<<98, 1024>>>();
    k_scanC2<<<392, 256>>>();
    k_fill<<<6250, 256>>>(ei);

    cudaStreamWaitEvent(0, eJoin, 0);     // join: agg32 needs both g_U and CSR

    for (int l = 0; l < NL; l++) {
        k_agg32<<<AB, 256>>>(eps, l, b1 + l * HH);
        k_gemm32<<<GB, 256>>>(0, l, W2 + l * HH * HH, b2 + l * HH,
                              g1 + l * HH, bt1 + l * HH, -1);
        if (l < NL - 1) {
            k_gemm32<<<GB, 256>>>(1, l, (const float*)0, (const float*)0,
                                  g2 + l * HH, bt2 + l * HH, l);
        } else {
            k_gemm3<<<GB, 256>>>(l, W3 + l * DD * HH, b3 + l * DD,
                                 g2 + l * HH, bt2 + l * HH, (float4*)d_out);
        }
    }

    cudaEventDestroy(eFork);
    cudaEventDestroy(eJoin);
    cudaStreamDestroy(s2);
}